// round 5
// baseline (speedup 1.0000x reference)
#include <cuda_runtime.h>

// ContrastHead: neighbor-contrastive loss.
//   N=200000 points, K=16 neighbors, C=32 features, T=0.1, weight=0.1, eps=1e-8
// Inputs: features f32 [N*C], labels i32 [N], neighbor_idx [N*K] (int32/int64 runtime-detect)
// Output: 1 float.
//
// R5: R1 was L1tex wavefront-replay-bound (~34 wf/pt x 2.07 cyc). The 16 random label
// lines per point move to a shared-memory u8 table (196KB, persistent blocks) -> LDS
// crossbar instead of L1tex. Feature gather stays f32 quarter-warp (16 wf/pt, minimal).
// Capture-safe: attribute set only when not capturing; path chosen by attribute readback.

#define KNB 16
#define CF  32
#define NBLOCKS 148
#define THREADS 1024
#define SMEM_BYTES 200704   // >= N bytes, 16B-aligned; well under the ~227KB opt-in max

__device__ __align__(16) unsigned char g_lab8[200704];
__device__ float2 g_part[NBLOCKS];

// labels i32 -> u8 (classes < 17). 4 labels per thread.
__global__ __launch_bounds__(256) void ch_pack_kernel(
    const int* __restrict__ labels, int n)
{
    const int k = blockIdx.x * blockDim.x + threadIdx.x;
    const int base = 4 * k;
    if (base >= n) return;
    uchar4 o;
    o.x = (unsigned char)labels[base];
    o.y = (unsigned char)labels[(base + 1 < n) ? base + 1 : n - 1];
    o.z = (unsigned char)labels[(base + 2 < n) ? base + 2 : n - 1];
    o.w = (unsigned char)labels[(base + 3 < n) ? base + 3 : n - 1];
    reinterpret_cast<uchar4*>(g_lab8)[k] = o;
}

template <bool USE_SMEM>
__global__ __launch_bounds__(THREADS) void ch_main_kernel(
    const float* __restrict__ feat,
    const void*  __restrict__ nbr,
    int n, int chunk)
{
    extern __shared__ unsigned char s_lab[];

    if (USE_SMEM) {
        const int nvec = (n + 15) >> 4;
        const uint4* src = reinterpret_cast<const uint4*>(g_lab8);
        uint4* dst = reinterpret_cast<uint4*>(s_lab);
        for (int i = threadIdx.x; i < nvec; i += THREADS) dst[i] = src[i];
        __syncthreads();
    }
    const unsigned char* __restrict__ ltab = USE_SMEM ? s_lab : g_lab8;

    const unsigned FULL = 0xffffffffu;
    const int lane = threadIdx.x & 31;
    const int wid  = threadIdx.x >> 5;

    // dtype detect: int64 -> odd 32-bit words of first 16 entries all zero.
    int probe = 1;
    if (lane < 16) probe = reinterpret_cast<const int*>(nbr)[2 * lane + 1];
    const bool is64 = ((__ballot_sync(FULL, probe == 0) & 0xFFFFu) == 0xFFFFu);

    const int base = blockIdx.x * chunk;
    const int end  = (base + chunk < n) ? (base + chunk) : n;

    float acc_num = 0.0f, acc_den = 0.0f;

    for (int p = base + wid; p < end; p += THREADS / 32) {
        // lanes 0..15: neighbor index (one coalesced line)
        int myidx = 0;
        if (lane < KNB) {
            if (is64)
                myidx = (int)reinterpret_cast<const long long*>(nbr)[(size_t)p * KNB + lane];
            else
                myidx = reinterpret_cast<const int*>(nbr)[(size_t)p * KNB + lane];
        }
        const int lab   = ltab[p];
        const int nblab = ltab[(lane < KNB) ? myidx : 0];

        // quarter-warp layout: sublane s holds float4 chunk s of any 128B row
        const int s = lane & 7;
        const float4 cf = reinterpret_cast<const float4*>(feat + (size_t)p * CF)[s];

        float dist2 = 0.0f;
#pragma unroll
        for (int t = 0; t < 4; t++) {
            const int j_src = t * 4 + (lane >> 3);
            const int idx = __shfl_sync(FULL, myidx, j_src);
            const float4 nf = reinterpret_cast<const float4*>(feat + (size_t)idx * CF)[s];
            const float d0 = cf.x - nf.x, d1 = cf.y - nf.y;
            const float d2 = cf.z - nf.z, d3 = cf.w - nf.w;
            float sum = d0 * d0;
            sum = fmaf(d1, d1, sum);
            sum = fmaf(d2, d2, sum);
            sum = fmaf(d3, d3, sum);
            sum += __shfl_xor_sync(FULL, sum, 4);
            sum += __shfl_xor_sync(FULL, sum, 2);
            sum += __shfl_xor_sync(FULL, sum, 1);
            // quarter q's total lives at lane q*8; route to owner lane t*4+q
            const float cand = __shfl_sync(FULL, sum, (lane & 3) << 3);
            if ((lane >> 2) == t) dist2 = cand;
        }

        const float nd = (lane < KNB) ? -sqrtf(dist2 + 1e-8f) : -1e30f;

        // softmax max over neighbor lanes (xor<16 stays in lower half)
        float m = nd;
        m = fmaxf(m, __shfl_xor_sync(FULL, m, 8));
        m = fmaxf(m, __shfl_xor_sync(FULL, m, 4));
        m = fmaxf(m, __shfl_xor_sync(FULL, m, 2));
        m = fmaxf(m, __shfl_xor_sync(FULL, m, 1));

        const float e = (lane < KNB) ? __expf((nd - m) * 10.0f) : 0.0f;  // 1/T = 10
        const bool ispos = (lane < KNB) && (nblab == lab);
        float pos = ispos ? e : 0.0f;
        float neg = e;
#pragma unroll
        for (int off = 8; off >= 1; off >>= 1) {
            pos += __shfl_xor_sync(FULL, pos, off);
            neg += __shfl_xor_sync(FULL, neg, off);
        }
        const int cnt = __popc(__ballot_sync(FULL, ispos) & 0xFFFFu);

        if (lane == 0) {
            const float pm = (cnt > 0 && cnt < KNB) ? 1.0f : 0.0f;
            const float loss = -__logf(pos / neg + 1e-8f);
            acc_num = fmaf(loss, pm, acc_num);
            acc_den += pm;
        }
    }

    __shared__ float sn[32], sd[32];
    if (lane == 0) { sn[wid] = acc_num; sd[wid] = acc_den; }
    __syncthreads();
    if (threadIdx.x < 32) {
        float a = sn[threadIdx.x], b = sd[threadIdx.x];
#pragma unroll
        for (int off = 16; off >= 1; off >>= 1) {
            a += __shfl_xor_sync(FULL, a, off);
            b += __shfl_xor_sync(FULL, b, off);
        }
        if (threadIdx.x == 0) g_part[blockIdx.x] = make_float2(a, b);
    }
}

__global__ __launch_bounds__(256) void ch_finalize_kernel(float* __restrict__ out)
{
    const unsigned FULL = 0xffffffffu;
    float a = 0.0f, b = 0.0f;
    for (int i = threadIdx.x; i < NBLOCKS; i += 256) {
        float2 v = g_part[i];
        a += v.x; b += v.y;
    }
#pragma unroll
    for (int off = 16; off >= 1; off >>= 1) {
        a += __shfl_xor_sync(FULL, a, off);
        b += __shfl_xor_sync(FULL, b, off);
    }
    __shared__ float sa[8], sb[8];
    if ((threadIdx.x & 31) == 0) { sa[threadIdx.x >> 5] = a; sb[threadIdx.x >> 5] = b; }
    __syncthreads();
    if (threadIdx.x == 0) {
        double na = 0.0, nb = 0.0;
#pragma unroll
        for (int i = 0; i < 8; i++) { na += sa[i]; nb += sb[i]; }
        if (nb < 1.0) nb = 1.0;
        out[0] = (float)(na / nb * 0.1);   // WEIGHT = 0.1
    }
}

extern "C" void kernel_launch(void* const* d_in, const int* in_sizes, int n_in,
                              void* d_out, int out_size) {
    const float* feat   = (const float*)d_in[0];
    const int*   labels = (const int*)d_in[1];
    const void*  nbr    = (const void*)d_in[2];
    float* out = (float*)d_out;
    (void)n_in; (void)out_size;

    const int n = in_sizes[1];   // N points

    // Capture-safe opt-in smem setup (stateless; queries are capture-legal,
    // the attribute set is only issued outside capture and is idempotent).
    cudaStreamCaptureStatus st = cudaStreamCaptureStatusNone;
    cudaStreamIsCapturing(0, &st);
    cudaFuncAttributes fa{};
    cudaFuncGetAttributes(&fa, ch_main_kernel<true>);
    if (fa.maxDynamicSharedSizeBytes < SMEM_BYTES &&
        st == cudaStreamCaptureStatusNone) {
        cudaFuncSetAttribute(ch_main_kernel<true>,
                             cudaFuncAttributeMaxDynamicSharedMemorySize, SMEM_BYTES);
        cudaFuncGetAttributes(&fa, ch_main_kernel<true>);
    }
    const bool use_smem = (fa.maxDynamicSharedSizeBytes >= SMEM_BYTES) &&
                          (n <= SMEM_BYTES);

    ch_pack_kernel<<<((n + 3) / 4 + 255) / 256, 256>>>(labels, n);

    const int chunk = (n + NBLOCKS - 1) / NBLOCKS;
    if (use_smem)
        ch_main_kernel<true><<<NBLOCKS, THREADS, SMEM_BYTES>>>(feat, nbr, n, chunk);
    else
        ch_main_kernel<false><<<NBLOCKS, THREADS, 0>>>(feat, nbr, n, chunk);

    ch_finalize_kernel<<<1, 256>>>(out);
}